// round 6
// baseline (speedup 1.0000x reference)
#include <cuda_runtime.h>
#include <math.h>

#define BB 8
#define QQ 2048
#define GG 128
#define CC 512
#define TOPK 160   // >=129 needed (at most 127 cols ever matched); 5 warp-rounds

// Transposed cost scratch: [b][g][q], contiguous in q (feeds the sort).
__device__ float g_costT[BB * GG * QQ];
// Per (b,row) sorted smallest-TOPK entries, packed (ord32(val)<<32)|col(1-based).
__device__ unsigned long long g_top[BB * GG * TOPK];

// ---------------------------------------------------------------------------
// float<->ordered helpers
// ---------------------------------------------------------------------------
__device__ __forceinline__ unsigned int ord32(float f) {
    unsigned int u = __float_as_uint(f);
    return (u & 0x80000000u) ? ~u : (u | 0x80000000u);
}
__device__ __forceinline__ float unord32(unsigned int o) {
    unsigned int u = (o & 0x80000000u) ? (o ^ 0x80000000u) : ~o;
    return __uint_as_float(u);
}
__device__ __forceinline__ unsigned long long ord64(double d) {
    unsigned long long u = (unsigned long long)__double_as_longlong(d);
    return (u >> 63) ? ~u : (u | 0x8000000000000000ull);
}
__device__ __forceinline__ double unord64(unsigned long long o) {
    unsigned long long u = (o >> 63) ? (o ^ 0x8000000000000000ull) : ~o;
    return __longlong_as_double((long long)u);
}

// ---------------------------------------------------------------------------
// Kernel 1: fused focal-class cost + regression costs, with tiled transpose
// so BOTH the [b][q][g] output and the [b][g][q] scratch are written
// fully coalesced. Block = 256 threads covering a 32q x 32g tile.
// ---------------------------------------------------------------------------
__global__ void __launch_bounds__(256)
cost_kernel(const float* __restrict__ sem,
            const float* __restrict__ cen,
            const float* __restrict__ siz,
            const float* __restrict__ gio,
            const int* __restrict__ lab,
            float* __restrict__ out_cost) {
    __shared__ float tile[32][33];
    __shared__ int   lab_s[32];

    int blk = blockIdx.x;                 // (b * 4 + gt) * 64 + qt
    int qt  = blk & 63;
    int gt  = (blk >> 6) & 3;
    int b   = blk >> 8;

    int tx = threadIdx.x & 31;            // g within tile
    int ty = threadIdx.x >> 5;            // q sub-row (0..7)
    int g0 = gt * 32;
    int q0 = qt * 32;

    if (threadIdx.x < 32) lab_s[tx] = lab[b * GG + g0 + tx];
    __syncthreads();

    int l = lab_s[tx];
    #pragma unroll
    for (int s = 0; s < 4; ++s) {
        int ql = ty + 8 * s;
        int q  = q0 + ql;
        long long idx = ((long long)(b * QQ + q)) * GG + g0 + tx;

        float x = sem[((long long)(b * QQ + q)) * CC + l];
        float p   = 1.0f / (1.0f + expf(-x));
        float neg = 0.75f * p * p * (-log1pf(-(p - 1e-8f)));
        float pos = 0.25f * (1.0f - p) * (1.0f - p) * (-logf(p + 1e-8f));
        float cost = 2.0f * (pos - neg) + 5.0f * cen[idx] + siz[idx]
                     - 2.0f * gio[idx];

        out_cost[idx]  = cost;
        tile[ql][tx] = cost;
    }
    __syncthreads();

    #pragma unroll
    for (int s = 0; s < 4; ++s) {
        int gl = ty + 8 * s;
        g_costT[((long long)(b * GG + g0 + gl)) * QQ + q0 + tx] = tile[tx][gl];
    }
}

// ---------------------------------------------------------------------------
// Kernel 2: per (b,row) full bitonic sort of 2048 packed keys; keep TOPK.
// Ascending by (value, column index) — exactly numpy's argmin tie-break.
// ---------------------------------------------------------------------------
__global__ void __launch_bounds__(512)
sort_kernel() {
    __shared__ unsigned long long s[QQ];
    int tid = threadIdx.x;
    const float* rowp = g_costT + (size_t)blockIdx.x * QQ;

    #pragma unroll
    for (int t = 0; t < QQ / 512; ++t) {
        int j = tid + t * 512;
        s[j] = ((unsigned long long)ord32(rowp[j]) << 32) | (unsigned int)(j + 1);
    }
    __syncthreads();

    for (int k = 2; k <= QQ; k <<= 1) {
        for (int jj = k >> 1; jj > 0; jj >>= 1) {
            #pragma unroll
            for (int t = 0; t < QQ / 512; ++t) {
                int i = tid + t * 512;
                int l = i ^ jj;
                if (l > i) {
                    unsigned long long a = s[i], c = s[l];
                    bool asc = ((i & k) == 0);
                    if (asc ? (a > c) : (a < c)) { s[i] = c; s[l] = a; }
                }
            }
            __syncthreads();
        }
    }
    if (tid < TOPK)
        g_top[(size_t)blockIdx.x * TOPK + tid] = s[tid];
}

// ---------------------------------------------------------------------------
// Kernel 3: one warp per batch. Replica of the reference's degenerate e-maxx
// loop. Steady-state inner iteration: cached probe (LDS) + 128-wide matched
// scan (registers/LDS) + shfl butterfly argmin. No atomics, no syncwarp in
// the chain step. used-flags live in per-lane registers.
// ---------------------------------------------------------------------------
struct SmemLSA {
    float  Mc[GG * 129];          // Mc[slot*129 + (row-1)]
    double v_s[GG];
    double u_s[GG + 1];
    double Dj[GG + 2];
    int    chain_slot[GG + 2];
    int    chain_row[GG + 2];
    int    slot_col[GG];
    int    pc_col[GG + 1];        // cached first-unmatched col per row (0=invalid)
    float  pc_val[GG + 1];
    int    cursor[GG + 1];
    unsigned char col2slot[QQ + 2];   // 0xFF = unmatched
    unsigned char slot_row[GG];
};

__global__ void __launch_bounds__(32, 1)
lsa_kernel(const int* __restrict__ nactual,
           const float* __restrict__ cost_bqg,
           float* __restrict__ out_inds,
           float* __restrict__ out_mask) {
    extern __shared__ unsigned char smraw[];
    SmemLSA& S = *reinterpret_cast<SmemLSA*>(smraw);

    int b    = blockIdx.x;
    int lane = threadIdx.x;
    int n = nactual[b];
    if (n > GG) n = GG;
    if (n < 0) n = 0;

    for (int t = lane; t <= GG; t += 32) {
        S.u_s[t] = 0.0; S.pc_col[t] = 0; S.cursor[t] = 0;
    }
    for (int t = lane; t <= QQ; t += 32) S.col2slot[t] = 0xFF;
    __syncwarp();

    const unsigned long long* top = g_top + (size_t)b * GG * TOPK;
    const float* costb = cost_bqg + (size_t)b * QQ * GG;
    int mcount = 0;

    for (int i = 1; i <= n; ++i) {
        unsigned um = 0;             // per-lane used mask over owned slots
        int cl = 1, row = i, j1;
        double D = 0.0;
        if (lane == 0) { S.chain_row[0] = i; S.Dj[0] = 0.0; }
        __syncwarp();

        while (true) {
            double u_row = S.u_s[row];

            // --- probe: cached first-unmatched entry; refresh if invalid ---
            if (S.pc_col[row] == 0) {
                const unsigned long long* trow = top + (size_t)(row - 1) * TOPK;
                int cur = S.cursor[row];
                for (int r = cur >> 5; r < TOPK / 32; ++r) {
                    unsigned long long e = __ldg(&trow[r * 32 + lane]);
                    int c = (int)(unsigned int)(e & 0xFFFFFFFFu);
                    unsigned m = __ballot_sync(0xffffffffu,
                                               S.col2slot[c] == 0xFF);
                    if (m) {
                        int f = __ffs(m) - 1;
                        unsigned long long ew = __shfl_sync(0xffffffffu, e, f);
                        if (lane == 0) {
                            S.pc_col[row]  = (int)(unsigned int)(ew & 0xFFFFFFFFu);
                            S.pc_val[row]  = unord32((unsigned int)(ew >> 32));
                            S.cursor[row]  = r * 32 + f;
                        }
                        break;
                    }
                }
            }

            // --- matched-column candidates (registers + shared cache) ---
            unsigned long long bk = ~0ull;
            int bc = 0x7fffffff;
            #pragma unroll
            for (int t = 0; t < 4; ++t) {
                int slot = lane + t * 32;
                if (slot < mcount && !((um >> t) & 1u)) {
                    double k = ((double)S.Mc[slot * 129 + (row - 1)] - u_row)
                               - S.v_s[slot];
                    unsigned long long o = ord64(k);
                    int c = S.slot_col[slot];
                    if (o < bk || (o == bk && c < bc)) { bk = o; bc = c; }
                }
            }
            if (lane == 0) {
                int c = S.pc_col[row];
                if (c != 0) {
                    double pk = (double)S.pc_val[row] - u_row;
                    unsigned long long o = ord64(pk);
                    if (o < bk || (o == bk && c < bc)) { bk = o; bc = c; }
                }
            }
            // --- butterfly argmin reduce (tie -> lowest col) ---
            #pragma unroll
            for (int off = 16; off; off >>= 1) {
                unsigned long long ok = __shfl_xor_sync(0xffffffffu, bk, off);
                int oc = __shfl_xor_sync(0xffffffffu, bc, off);
                if (ok < bk || (ok == bk && oc < bc)) { bk = ok; bc = oc; }
            }

            j1 = bc;
            D += unord64(bk);

            int slot1 = S.col2slot[j1];
            if (slot1 != 0xFF) {         // chase occupied column
                if ((slot1 & 31) == lane) um |= 1u << (slot1 >> 5);
                int nrow = S.slot_row[slot1];
                if (lane == 0) {
                    S.chain_slot[cl] = slot1;
                    S.chain_row[cl]  = nrow;
                    S.Dj[cl]         = D;
                }
                row = nrow;
                ++cl;
            } else break;                // free column: augment
        }
        __syncwarp();

        // fill Mc column for the new match (column-contiguous in cost_bqg)
        {
            float4 src = *(const float4*)(costb + (size_t)(j1 - 1) * GG + lane * 4);
            float* dst = &S.Mc[mcount * 129 + lane * 4];
            dst[0] = src.x; dst[1] = src.y; dst[2] = src.z; dst[3] = src.w;
        }
        // deferred potential updates along the chain (rows/slots distinct)
        for (int t = lane; t < cl; t += 32) {
            double acc = D - S.Dj[t];
            S.u_s[S.chain_row[t]] += acc;
            if (t > 0) S.v_s[S.chain_slot[t]] -= acc;
        }
        // invalidate cached probes that pointed at the newly matched column
        #pragma unroll
        for (int t = 0; t < 4; ++t) {
            int r = 1 + lane + t * 32;
            if (r <= GG && S.pc_col[r] == j1) S.pc_col[r] = 0;
        }
        if (lane == 0) {
            S.col2slot[j1]     = (unsigned char)mcount;
            S.slot_row[mcount] = (unsigned char)i;
            S.slot_col[mcount] = j1;
            S.v_s[mcount]      = 0.0;    // terminal column: no v update yet
        }
        ++mcount;
        __syncwarp();
    }

    // emit per-proposal matches
    for (int j = lane; j < QQ; j += 32) {
        unsigned char s = S.col2slot[j + 1];
        float ind = 0.0f, mskv = 0.0f;
        if (s != 0xFF) { ind = (float)(S.slot_row[s] - 1); mskv = 1.0f; }
        out_inds[b * QQ + j] = ind;
        out_mask[b * QQ + j] = mskv;
    }
}

// ---------------------------------------------------------------------------
extern "C" void kernel_launch(void* const* d_in, const int* in_sizes, int n_in,
                              void* d_out, int out_size) {
    const float* sem = (const float*)d_in[0];
    const float* cen = (const float*)d_in[1];
    const float* siz = (const float*)d_in[2];
    const float* gio = (const float*)d_in[3];
    const int*   lab = (const int*)d_in[4];
    const int*   na  = (const int*)d_in[5];

    float* out = (float*)d_out;
    const int NI = BB * QQ;
    const int NC = BB * QQ * GG;

    float* out_inds = out;
    float* out_mask = out + NI;
    float* out_cost = out + 2 * NI;
    bool   do_lsa   = true;
    if (out_size == NC) { out_cost = out; do_lsa = false; }

    cost_kernel<<<BB * 4 * 64, 256>>>(sem, cen, siz, gio, lab, out_cost);
    if (do_lsa) {
        sort_kernel<<<BB * GG, 512>>>();
        static bool attr_set = false;
        if (!attr_set) {
            cudaFuncSetAttribute(lsa_kernel,
                                 cudaFuncAttributeMaxDynamicSharedMemorySize,
                                 (int)sizeof(SmemLSA));
            attr_set = true;
        }
        lsa_kernel<<<BB, 32, sizeof(SmemLSA)>>>(na, out_cost, out_inds, out_mask);
    }
}

// round 7
// speedup vs baseline: 1.0248x; 1.0248x over previous
#include <cuda_runtime.h>
#include <math.h>

#define BB 8
#define QQ 2048
#define GG 128
#define CC 512
#define TOPK 160     // >=128 needed (at most 127 cols matched when probing)
#define MCW 136      // Mc row stride (floats): 16B-aligned float4, conflict-free scan

// Transposed cost scratch: [b][g][q], contiguous in q (feeds the sort).
__device__ float g_costT[BB * GG * QQ];
// Per (b,row) sorted smallest-TOPK entries, packed (ord32(val)<<32)|col(1-based).
__device__ unsigned long long g_top[BB * GG * TOPK];

// ---------------------------------------------------------------------------
__device__ __forceinline__ unsigned int ord32(float f) {
    unsigned int u = __float_as_uint(f);
    return (u & 0x80000000u) ? ~u : (u | 0x80000000u);
}
__device__ __forceinline__ float unord32(unsigned int o) {
    unsigned int u = (o & 0x80000000u) ? (o ^ 0x80000000u) : ~o;
    return __uint_as_float(u);
}
__device__ __forceinline__ unsigned long long ord64(double d) {
    unsigned long long u = (unsigned long long)__double_as_longlong(d);
    return (u >> 63) ? ~u : (u | 0x8000000000000000ull);
}
__device__ __forceinline__ double unord64(unsigned long long o) {
    unsigned long long u = (o >> 63) ? (o ^ 0x8000000000000000ull) : ~o;
    return __longlong_as_double((long long)u);
}

// ---------------------------------------------------------------------------
// Kernel 1: fused focal-class cost + regression costs, tiled transpose so
// both the [b][q][g] output and the [b][g][q] scratch are coalesced.
// ---------------------------------------------------------------------------
__global__ void __launch_bounds__(256)
cost_kernel(const float* __restrict__ sem,
            const float* __restrict__ cen,
            const float* __restrict__ siz,
            const float* __restrict__ gio,
            const int* __restrict__ lab,
            float* __restrict__ out_cost) {
    __shared__ float tile[32][33];
    __shared__ int   lab_s[32];

    int blk = blockIdx.x;                 // (b * 4 + gt) * 64 + qt
    int qt  = blk & 63;
    int gt  = (blk >> 6) & 3;
    int b   = blk >> 8;

    int tx = threadIdx.x & 31;            // g within tile
    int ty = threadIdx.x >> 5;            // q sub-row (0..7)
    int g0 = gt * 32;
    int q0 = qt * 32;

    if (threadIdx.x < 32) lab_s[tx] = lab[b * GG + g0 + tx];
    __syncthreads();

    int l = lab_s[tx];
    #pragma unroll
    for (int s = 0; s < 4; ++s) {
        int ql = ty + 8 * s;
        int q  = q0 + ql;
        long long idx = ((long long)(b * QQ + q)) * GG + g0 + tx;

        float x = sem[((long long)(b * QQ + q)) * CC + l];
        float p   = 1.0f / (1.0f + expf(-x));
        float neg = 0.75f * p * p * (-log1pf(-(p - 1e-8f)));
        float pos = 0.25f * (1.0f - p) * (1.0f - p) * (-logf(p + 1e-8f));
        float cost = 2.0f * (pos - neg) + 5.0f * cen[idx] + siz[idx]
                     - 2.0f * gio[idx];

        out_cost[idx] = cost;
        tile[ql][tx]  = cost;
    }
    __syncthreads();

    #pragma unroll
    for (int s = 0; s < 4; ++s) {
        int gl = ty + 8 * s;
        g_costT[((long long)(b * GG + g0 + gl)) * QQ + q0 + tx] = tile[tx][gl];
    }
}

// ---------------------------------------------------------------------------
// Kernel 2: per (b,row) bitonic sort of 2048 packed keys; keep TOPK.
// ---------------------------------------------------------------------------
__global__ void __launch_bounds__(512)
sort_kernel() {
    __shared__ unsigned long long s[QQ];
    int tid = threadIdx.x;
    const float* rowp = g_costT + (size_t)blockIdx.x * QQ;

    #pragma unroll
    for (int t = 0; t < QQ / 512; ++t) {
        int j = tid + t * 512;
        s[j] = ((unsigned long long)ord32(rowp[j]) << 32) | (unsigned int)(j + 1);
    }
    __syncthreads();

    for (int k = 2; k <= QQ; k <<= 1) {
        for (int jj = k >> 1; jj > 0; jj >>= 1) {
            #pragma unroll
            for (int t = 0; t < QQ / 512; ++t) {
                int i = tid + t * 512;
                int l = i ^ jj;
                if (l > i) {
                    unsigned long long a = s[i], c = s[l];
                    bool asc = ((i & k) == 0);
                    if (asc ? (a > c) : (a < c)) { s[i] = c; s[l] = a; }
                }
            }
            __syncthreads();
        }
    }
    if (tid < TOPK)
        g_top[(size_t)blockIdx.x * TOPK + tid] = s[tid];
}

// ---------------------------------------------------------------------------
// Kernel 3: one warp per batch; reference's degenerate e-maxx loop.
// Steady-state iteration: 1x LDS.128 matched scan (slots/v/cols in regs),
// cached probe, u_row cancelled out of the argmin, 3x REDUX reduction,
// parallel col2slot/col2row lookups. Potentials deferred to augmentation.
// ---------------------------------------------------------------------------
struct SmemLSA {
    float  Mc[GG * MCW];          // row-major [row-1][slot], padded stride
    double u_s[GG + 2];
    double Dj[GG + 4];
    int    chain_slot[GG + 4];
    int    chain_row[GG + 4];
    int    pc_col[GG + 2];        // cached first-unmatched col per row (0=none)
    float  pc_val[GG + 2];
    int    cursor[GG + 2];
    int    srow_out[GG];
    unsigned char col2slot[QQ + 4];   // 0xFF = unmatched
    unsigned char col2row[QQ + 4];
};

__global__ void __launch_bounds__(32, 1)
lsa_kernel(const int* __restrict__ nactual,
           const float* __restrict__ cost_bqg,
           float* __restrict__ out_inds,
           float* __restrict__ out_mask) {
    extern __shared__ unsigned char smraw[];
    SmemLSA& S = *reinterpret_cast<SmemLSA*>(smraw);

    const unsigned FULL = 0xffffffffu;
    int b    = blockIdx.x;
    int lane = threadIdx.x;
    int n = nactual[b];
    if (n > GG) n = GG;
    if (n < 0) n = 0;

    for (int t = lane; t < GG + 2; t += 32) {
        S.u_s[t] = 0.0; S.pc_col[t] = 0; S.cursor[t] = 0;
    }
    for (int t = lane; t < QQ + 4; t += 32) S.col2slot[t] = 0xFF;
    __syncwarp();

    const unsigned long long* top = g_top + (size_t)b * GG * TOPK;
    const float* costb = cost_bqg + (size_t)b * QQ * GG;

    // Per-lane slot state: lane owns slots 4*lane .. 4*lane+3.
    double v_r[4];
    int    col_r[4], row_r[4];
    int mcount = 0;

    for (int i = 1; i <= n; ++i) {
        unsigned um = 0;
        int cl = 1, row = i, j1;
        double D = 0.0;
        if (lane == 0) { S.chain_row[0] = i; S.Dj[0] = 0.0; }
        __syncwarp();

        while (true) {
            // --- probe: cached first-unmatched entry; refresh if invalid ---
            int pcc = S.pc_col[row];
            if (pcc == 0) {
                const unsigned long long* trow = top + (size_t)(row - 1) * TOPK;
                int cur = S.cursor[row];
                for (int r = cur >> 5; r < TOPK / 32; ++r) {
                    unsigned long long e = __ldg(&trow[r * 32 + lane]);
                    int c = (int)(unsigned int)(e & 0xFFFFFFFFu);
                    unsigned m = __ballot_sync(FULL, S.col2slot[c] == 0xFF);
                    if (m) {
                        int f = __ffs(m) - 1;
                        unsigned long long ew = __shfl_sync(FULL, e, f);
                        if (lane == 0) {
                            S.pc_col[row] = (int)(unsigned int)(ew & 0xFFFFFFFFu);
                            S.pc_val[row] = unord32((unsigned int)(ew >> 32));
                            S.cursor[row] = r * 32 + f;
                        }
                        break;
                    }
                }
                __syncwarp();
                pcc = S.pc_col[row];
            }
            float  pval  = S.pc_val[row];
            double u_row = S.u_s[row];

            // --- matched-slot keys: one LDS.128, v in regs (u_row cancels) ---
            const float4 mc = *(const float4*)&S.Mc[(row - 1) * MCW + 4 * lane];
            unsigned long long k[4];
            int base = 4 * lane;
            {
                float mcf[4] = {mc.x, mc.y, mc.z, mc.w};
                #pragma unroll
                for (int t = 0; t < 4; ++t) {
                    bool act = (base + t < mcount) && !((um >> t) & 1u);
                    k[t] = act ? ord64((double)mcf[t] - v_r[t]) : ~0ull;
                }
            }
            unsigned long long bk = k[0];
            if (k[1] < bk) bk = k[1];
            if (k[2] < bk) bk = k[2];
            if (k[3] < bk) bk = k[3];
            unsigned long long kp = ~0ull;
            if (lane == 0) {
                kp = ord64((double)pval);
                if (kp < bk) bk = kp;
            }

            // --- 3-stage REDUX argmin (tie -> lowest col) ---
            unsigned hi = (unsigned)(bk >> 32);
            unsigned hmin = __reduce_min_sync(FULL, hi);
            unsigned lo = (hi == hmin) ? (unsigned)bk : 0xFFFFFFFFu;
            unsigned lmin = __reduce_min_sync(FULL, lo);
            unsigned long long gmin =
                ((unsigned long long)hmin << 32) | lmin;
            unsigned cc = 0xFFFFFFFFu;
            #pragma unroll
            for (int t = 0; t < 4; ++t)
                if (k[t] == gmin) cc = min(cc, (unsigned)col_r[t]);
            if (lane == 0 && kp == gmin) cc = min(cc, (unsigned)pcc);
            j1 = (int)__reduce_min_sync(FULL, cc);

            D += unord64(gmin) - u_row;

            int slot1 = S.col2slot[j1];
            if (slot1 != 0xFF) {          // chase occupied column
                int nrow = S.col2row[j1];
                if ((slot1 >> 2) == lane) um |= 1u << (slot1 & 3);
                if (lane == 0) {
                    S.chain_slot[cl] = slot1;
                    S.chain_row[cl]  = nrow;
                    S.Dj[cl]         = D;
                }
                row = nrow;
                ++cl;
            } else break;                 // free column: augment
        }
        __syncwarp();

        // ---- augmentation (off critical path) ----
        // Mc fill: column j1 of costb into Mc[*][mcount]
        {
            const float* colp = costb + (size_t)(j1 - 1) * GG;
            #pragma unroll
            for (int m = 0; m < 4; ++m) {
                int r = lane + 32 * m;
                S.Mc[r * MCW + mcount] = __ldg(&colp[r]);
            }
        }
        // deferred u updates (chain rows distinct)
        for (int t = lane; t < cl; t += 32) {
            S.u_s[S.chain_row[t]] += D - S.Dj[t];
        }
        // deferred v updates: each lane applies chain entries owning its slots
        for (int t = 1; t < cl; ++t) {
            int s = S.chain_slot[t];
            if ((s >> 2) == lane) {
                double acc = D - S.Dj[t];
                switch (s & 3) {
                    case 0: v_r[0] -= acc; break;
                    case 1: v_r[1] -= acc; break;
                    case 2: v_r[2] -= acc; break;
                    case 3: v_r[3] -= acc; break;
                }
            }
        }
        // invalidate probe caches pointing at the newly matched column
        #pragma unroll
        for (int t = 0; t < 4; ++t) {
            int r = 1 + lane + 32 * t;
            if (S.pc_col[r] == j1) S.pc_col[r] = 0;
        }
        // register the new slot
        if ((mcount >> 2) == lane) {
            switch (mcount & 3) {
                case 0: v_r[0] = 0.0; col_r[0] = j1; row_r[0] = i; break;
                case 1: v_r[1] = 0.0; col_r[1] = j1; row_r[1] = i; break;
                case 2: v_r[2] = 0.0; col_r[2] = j1; row_r[2] = i; break;
                case 3: v_r[3] = 0.0; col_r[3] = j1; row_r[3] = i; break;
            }
        }
        if (lane == 0) {
            S.col2slot[j1] = (unsigned char)mcount;
            S.col2row[j1]  = (unsigned char)i;
        }
        ++mcount;
        __syncwarp();
    }

    // stage slot rows for emit
    #pragma unroll
    for (int t = 0; t < 4; ++t) {
        int s = 4 * lane + t;
        if (s < mcount) S.srow_out[s] = row_r[t];
    }
    __syncwarp();

    for (int j = lane; j < QQ; j += 32) {
        unsigned char s = S.col2slot[j + 1];
        float ind = 0.0f, mskv = 0.0f;
        if (s != 0xFF) { ind = (float)(S.col2row[j + 1] - 1); mskv = 1.0f; }
        out_inds[b * QQ + j] = ind;
        out_mask[b * QQ + j] = mskv;
    }
}

// ---------------------------------------------------------------------------
extern "C" void kernel_launch(void* const* d_in, const int* in_sizes, int n_in,
                              void* d_out, int out_size) {
    const float* sem = (const float*)d_in[0];
    const float* cen = (const float*)d_in[1];
    const float* siz = (const float*)d_in[2];
    const float* gio = (const float*)d_in[3];
    const int*   lab = (const int*)d_in[4];
    const int*   na  = (const int*)d_in[5];

    float* out = (float*)d_out;
    const int NI = BB * QQ;
    const int NC = BB * QQ * GG;

    float* out_inds = out;
    float* out_mask = out + NI;
    float* out_cost = out + 2 * NI;
    bool   do_lsa   = true;
    if (out_size == NC) { out_cost = out; do_lsa = false; }

    cost_kernel<<<BB * 4 * 64, 256>>>(sem, cen, siz, gio, lab, out_cost);
    if (do_lsa) {
        sort_kernel<<<BB * GG, 512>>>();
        static bool attr_set = false;
        if (!attr_set) {
            cudaFuncSetAttribute(lsa_kernel,
                                 cudaFuncAttributeMaxDynamicSharedMemorySize,
                                 (int)sizeof(SmemLSA));
            attr_set = true;
        }
        lsa_kernel<<<BB, 32, sizeof(SmemLSA)>>>(na, out_cost, out_inds, out_mask);
    }
}

// round 8
// speedup vs baseline: 1.0313x; 1.0063x over previous
#include <cuda_runtime.h>
#include <math.h>

#define BB 8
#define QQ 2048
#define GG 128
#define CC 512
#define TOPK 160     // >=128 needed (at most 127 cols matched when probing)
#define MCW 136      // Mc row stride (floats): 16B-aligned float4, conflict-free

// Transposed cost scratch: [b][g][q], contiguous in q (feeds the sort).
__device__ float g_costT[BB * GG * QQ];
// Per (b,row) sorted smallest-TOPK entries, packed (ord32(val)<<32)|col(1-based).
__device__ unsigned long long g_top[BB * GG * TOPK];

// ---------------------------------------------------------------------------
__device__ __forceinline__ unsigned int ord32(float f) {
    unsigned int u = __float_as_uint(f);
    return (u & 0x80000000u) ? ~u : (u | 0x80000000u);
}
__device__ __forceinline__ float unord32(unsigned int o) {
    unsigned int u = (o & 0x80000000u) ? (o ^ 0x80000000u) : ~o;
    return __uint_as_float(u);
}
__device__ __forceinline__ unsigned long long ord64(double d) {
    unsigned long long u = (unsigned long long)__double_as_longlong(d);
    return (u >> 63) ? ~u : (u | 0x8000000000000000ull);
}
__device__ __forceinline__ double unord64(unsigned long long o) {
    unsigned long long u = (o >> 63) ? (o ^ 0x8000000000000000ull) : ~o;
    return __longlong_as_double((long long)u);
}

// ---------------------------------------------------------------------------
// Kernel 1: fused focal-class cost + regression costs, tiled transpose.
// ---------------------------------------------------------------------------
__global__ void __launch_bounds__(256)
cost_kernel(const float* __restrict__ sem,
            const float* __restrict__ cen,
            const float* __restrict__ siz,
            const float* __restrict__ gio,
            const int* __restrict__ lab,
            float* __restrict__ out_cost) {
    __shared__ float tile[32][33];
    __shared__ int   lab_s[32];

    int blk = blockIdx.x;                 // (b * 4 + gt) * 64 + qt
    int qt  = blk & 63;
    int gt  = (blk >> 6) & 3;
    int b   = blk >> 8;

    int tx = threadIdx.x & 31;            // g within tile
    int ty = threadIdx.x >> 5;            // q sub-row (0..7)
    int g0 = gt * 32;
    int q0 = qt * 32;

    if (threadIdx.x < 32) lab_s[tx] = lab[b * GG + g0 + tx];
    __syncthreads();

    int l = lab_s[tx];
    #pragma unroll
    for (int s = 0; s < 4; ++s) {
        int ql = ty + 8 * s;
        int q  = q0 + ql;
        long long idx = ((long long)(b * QQ + q)) * GG + g0 + tx;

        float x = sem[((long long)(b * QQ + q)) * CC + l];
        float p   = 1.0f / (1.0f + expf(-x));
        float neg = 0.75f * p * p * (-log1pf(-(p - 1e-8f)));
        float pos = 0.25f * (1.0f - p) * (1.0f - p) * (-logf(p + 1e-8f));
        float cost = 2.0f * (pos - neg) + 5.0f * cen[idx] + siz[idx]
                     - 2.0f * gio[idx];

        out_cost[idx] = cost;
        tile[ql][tx]  = cost;
    }
    __syncthreads();

    #pragma unroll
    for (int s = 0; s < 4; ++s) {
        int gl = ty + 8 * s;
        g_costT[((long long)(b * GG + g0 + gl)) * QQ + q0 + tx] = tile[tx][gl];
    }
}

// ---------------------------------------------------------------------------
// Kernel 2: per (b,row) bitonic sort of 2048 packed keys; keep TOPK.
// ---------------------------------------------------------------------------
__global__ void __launch_bounds__(512)
sort_kernel() {
    __shared__ unsigned long long s[QQ];
    int tid = threadIdx.x;
    const float* rowp = g_costT + (size_t)blockIdx.x * QQ;

    #pragma unroll
    for (int t = 0; t < QQ / 512; ++t) {
        int j = tid + t * 512;
        s[j] = ((unsigned long long)ord32(rowp[j]) << 32) | (unsigned int)(j + 1);
    }
    __syncthreads();

    for (int k = 2; k <= QQ; k <<= 1) {
        for (int jj = k >> 1; jj > 0; jj >>= 1) {
            #pragma unroll
            for (int t = 0; t < QQ / 512; ++t) {
                int i = tid + t * 512;
                int l = i ^ jj;
                if (l > i) {
                    unsigned long long a = s[i], c = s[l];
                    bool asc = ((i & k) == 0);
                    if (asc ? (a > c) : (a < c)) { s[i] = c; s[l] = a; }
                }
            }
            __syncthreads();
        }
    }
    if (tid < TOPK)
        g_top[(size_t)blockIdx.x * TOPK + tid] = s[tid];
}

// ---------------------------------------------------------------------------
// Kernel 3: one warp per batch; reference's degenerate e-maxx loop.
// Col index packed into the low 12 bits of the ord64 key: argmin+tie-break
// collapses to min4 + two 32-bit REDUX. colinfo fuses slot/row/valid.
// ---------------------------------------------------------------------------
struct SmemLSA {
    float  Mc[GG * MCW];          // row-major [row-1][slot], padded stride
    double u_s[GG + 2];
    double Dj[GG + 4];
    int    chain_slot[GG + 4];
    int    chain_row[GG + 4];
    int    pc_col[GG + 2];        // cached first-unmatched col per row (0=none)
    float  pc_val[GG + 2];
    int    cursor[GG + 2];
    unsigned int colinfo[QQ + 4]; // 0 = unmatched; else 0x80000000|slot|(row<<8)
};

__global__ void __launch_bounds__(32, 1)
lsa_kernel(const int* __restrict__ nactual,
           const float* __restrict__ cost_bqg,
           float* __restrict__ out_inds,
           float* __restrict__ out_mask) {
    extern __shared__ unsigned char smraw[];
    SmemLSA& S = *reinterpret_cast<SmemLSA*>(smraw);

    const unsigned FULL = 0xffffffffu;
    int b    = blockIdx.x;
    int lane = threadIdx.x;
    int n = nactual[b];
    if (n > GG) n = GG;
    if (n < 0) n = 0;

    for (int t = lane; t < GG + 2; t += 32) {
        S.u_s[t] = 0.0; S.pc_col[t] = 0; S.cursor[t] = 0;
    }
    for (int t = lane; t < QQ + 4; t += 32) S.colinfo[t] = 0u;
    __syncwarp();

    const unsigned long long* top = g_top + (size_t)b * GG * TOPK;
    const float* costb = cost_bqg + (size_t)b * QQ * GG;

    // Per-lane slot state: lane owns slots 4*lane .. 4*lane+3.
    double v_r[4];
    int    col_r[4];
    int mcount = 0;

    for (int i = 1; i <= n; ++i) {
        unsigned um = 0;
        int cl = 1, row = i, j1;
        double D = 0.0;
        if (lane == 0) { S.chain_row[0] = i; S.Dj[0] = 0.0; }
        __syncwarp();

        while (true) {
            // --- probe: cached first-unmatched entry; refresh if invalid ---
            int pcc = S.pc_col[row];
            if (pcc == 0) {
                const unsigned long long* trow = top + (size_t)(row - 1) * TOPK;
                int cur = S.cursor[row];
                for (int r = cur >> 5; r < TOPK / 32; ++r) {
                    unsigned long long e = __ldg(&trow[r * 32 + lane]);
                    int c = (int)(unsigned int)(e & 0xFFFFFFFFu);
                    unsigned m = __ballot_sync(FULL, S.colinfo[c] == 0u);
                    if (m) {
                        int f = __ffs(m) - 1;
                        unsigned long long ew = __shfl_sync(FULL, e, f);
                        if (lane == 0) {
                            S.pc_col[row] = (int)(unsigned int)(ew & 0xFFFFFFFFu);
                            S.pc_val[row] = unord32((unsigned int)(ew >> 32));
                            S.cursor[row] = r * 32 + f;
                        }
                        break;
                    }
                }
                __syncwarp();
                pcc = S.pc_col[row];
            }
            float  pval  = S.pc_val[row];
            double u_row = S.u_s[row];

            // --- matched-slot keys: one LDS.128, v in regs (u_row cancels),
            //     col packed into low 12 bits of the ord64 key ---
            const float4 mc = *(const float4*)&S.Mc[(row - 1) * MCW + 4 * lane];
            unsigned long long k[4];
            int base = 4 * lane;
            {
                float mcf[4] = {mc.x, mc.y, mc.z, mc.w};
                #pragma unroll
                for (int t = 0; t < 4; ++t) {
                    bool act = (base + t < mcount) && !((um >> t) & 1u);
                    k[t] = act ? ((ord64((double)mcf[t] - v_r[t]) & ~0xFFFull)
                                  | (unsigned)col_r[t])
                               : ~0ull;
                }
            }
            unsigned long long a0 = (k[0] < k[1]) ? k[0] : k[1];
            unsigned long long a1 = (k[2] < k[3]) ? k[2] : k[3];
            unsigned long long bk = (a0 < a1) ? a0 : a1;
            if (lane == 0) {
                unsigned long long kp =
                    (ord64((double)pval) & ~0xFFFull) | (unsigned)pcc;
                if (kp < bk) bk = kp;
            }

            // --- 2-stage REDUX argmin (col tie-break baked into key) ---
            unsigned hi   = (unsigned)(bk >> 32);
            unsigned hmin = __reduce_min_sync(FULL, hi);
            unsigned lo   = (hi == hmin) ? (unsigned)bk : 0xFFFFFFFFu;
            unsigned lmin = __reduce_min_sync(FULL, lo);

            j1 = (int)(lmin & 0xFFFu);
            unsigned long long gmin =
                (((unsigned long long)hmin << 32) | lmin) & ~0xFFFull;
            D += unord64(gmin) - u_row;

            unsigned info = S.colinfo[j1];
            if (info) {                   // chase occupied column
                int slot1 = (int)(info & 0xFFu);
                int nrow  = (int)((info >> 8) & 0xFFu);
                if ((slot1 >> 2) == lane) um |= 1u << (slot1 & 3);
                if (lane == 0) {
                    S.chain_slot[cl] = slot1;
                    S.chain_row[cl]  = nrow;
                    S.Dj[cl]         = D;
                }
                row = nrow;
                ++cl;
            } else break;                 // free column: augment
        }
        __syncwarp();

        // ---- augmentation (off critical path) ----
        // Mc fill: column j1 of costb into Mc[*][mcount]
        {
            const float* colp = costb + (size_t)(j1 - 1) * GG;
            #pragma unroll
            for (int m = 0; m < 4; ++m) {
                int r = lane + 32 * m;
                S.Mc[r * MCW + mcount] = __ldg(&colp[r]);
            }
        }
        // deferred u updates (chain rows distinct)
        for (int t = lane; t < cl; t += 32) {
            S.u_s[S.chain_row[t]] += D - S.Dj[t];
        }
        // deferred v updates: each lane applies chain entries owning its slots
        for (int t = 1; t < cl; ++t) {
            int s = S.chain_slot[t];
            if ((s >> 2) == lane) {
                double acc = D - S.Dj[t];
                switch (s & 3) {
                    case 0: v_r[0] -= acc; break;
                    case 1: v_r[1] -= acc; break;
                    case 2: v_r[2] -= acc; break;
                    case 3: v_r[3] -= acc; break;
                }
            }
        }
        // invalidate probe caches pointing at the newly matched column
        #pragma unroll
        for (int t = 0; t < 4; ++t) {
            int r = 1 + lane + 32 * t;
            if (S.pc_col[r] == j1) S.pc_col[r] = 0;
        }
        // register the new slot
        if ((mcount >> 2) == lane) {
            switch (mcount & 3) {
                case 0: v_r[0] = 0.0; col_r[0] = j1; break;
                case 1: v_r[1] = 0.0; col_r[1] = j1; break;
                case 2: v_r[2] = 0.0; col_r[2] = j1; break;
                case 3: v_r[3] = 0.0; col_r[3] = j1; break;
            }
        }
        if (lane == 0) {
            S.colinfo[j1] = 0x80000000u | (unsigned)mcount | ((unsigned)i << 8);
        }
        ++mcount;
        __syncwarp();
    }

    // emit per-proposal matches
    for (int j = lane; j < QQ; j += 32) {
        unsigned info = S.colinfo[j + 1];
        float ind = 0.0f, mskv = 0.0f;
        if (info) { ind = (float)(((info >> 8) & 0xFFu) - 1); mskv = 1.0f; }
        out_inds[b * QQ + j] = ind;
        out_mask[b * QQ + j] = mskv;
    }
}

// ---------------------------------------------------------------------------
extern "C" void kernel_launch(void* const* d_in, const int* in_sizes, int n_in,
                              void* d_out, int out_size) {
    const float* sem = (const float*)d_in[0];
    const float* cen = (const float*)d_in[1];
    const float* siz = (const float*)d_in[2];
    const float* gio = (const float*)d_in[3];
    const int*   lab = (const int*)d_in[4];
    const int*   na  = (const int*)d_in[5];

    float* out = (float*)d_out;
    const int NI = BB * QQ;
    const int NC = BB * QQ * GG;

    float* out_inds = out;
    float* out_mask = out + NI;
    float* out_cost = out + 2 * NI;
    bool   do_lsa   = true;
    if (out_size == NC) { out_cost = out; do_lsa = false; }

    cost_kernel<<<BB * 4 * 64, 256>>>(sem, cen, siz, gio, lab, out_cost);
    if (do_lsa) {
        sort_kernel<<<BB * GG, 512>>>();
        static bool attr_set = false;
        if (!attr_set) {
            cudaFuncSetAttribute(lsa_kernel,
                                 cudaFuncAttributeMaxDynamicSharedMemorySize,
                                 (int)sizeof(SmemLSA));
            attr_set = true;
        }
        lsa_kernel<<<BB, 32, sizeof(SmemLSA)>>>(na, out_cost, out_inds, out_mask);
    }
}

// round 9
// speedup vs baseline: 1.1406x; 1.1060x over previous
#include <cuda_runtime.h>
#include <math.h>

#define BB 8
#define QQ 2048
#define GG 128
#define CC 512
#define TOPK 128     // exactly sufficient: <=127 cols matched at probe time
#define MCW 136      // Mc row stride (floats): 16B-aligned float4, conflict-free

// Transposed cost scratch: [b][g][q], contiguous in q (feeds the sort).
__device__ float g_costT[BB * GG * QQ];
// Per (b,row) sorted smallest-TOPK entries, packed (ord32(val)<<32)|col(1-based).
__device__ unsigned long long g_top[BB * GG * TOPK];

// ---------------------------------------------------------------------------
__device__ __forceinline__ unsigned int ord32(float f) {
    unsigned int u = __float_as_uint(f);
    return (u & 0x80000000u) ? ~u : (u | 0x80000000u);
}
__device__ __forceinline__ float unord32(unsigned int o) {
    unsigned int u = (o & 0x80000000u) ? (o ^ 0x80000000u) : ~o;
    return __uint_as_float(u);
}
__device__ __forceinline__ unsigned long long ord64(double d) {
    unsigned long long u = (unsigned long long)__double_as_longlong(d);
    return (u >> 63) ? ~u : (u | 0x8000000000000000ull);
}
__device__ __forceinline__ double unord64(unsigned long long o) {
    unsigned long long u = (o >> 63) ? (o ^ 0x8000000000000000ull) : ~o;
    return __longlong_as_double((long long)u);
}

// ---------------------------------------------------------------------------
// Kernel 1: fused focal-class cost + regression costs, tiled transpose.
// ---------------------------------------------------------------------------
__global__ void __launch_bounds__(256)
cost_kernel(const float* __restrict__ sem,
            const float* __restrict__ cen,
            const float* __restrict__ siz,
            const float* __restrict__ gio,
            const int* __restrict__ lab,
            float* __restrict__ out_cost) {
    __shared__ float tile[32][33];
    __shared__ int   lab_s[32];

    int blk = blockIdx.x;                 // (b * 4 + gt) * 64 + qt
    int qt  = blk & 63;
    int gt  = (blk >> 6) & 3;
    int b   = blk >> 8;

    int tx = threadIdx.x & 31;            // g within tile
    int ty = threadIdx.x >> 5;            // q sub-row (0..7)
    int g0 = gt * 32;
    int q0 = qt * 32;

    if (threadIdx.x < 32) lab_s[tx] = lab[b * GG + g0 + tx];
    __syncthreads();

    int l = lab_s[tx];
    #pragma unroll
    for (int s = 0; s < 4; ++s) {
        int ql = ty + 8 * s;
        int q  = q0 + ql;
        long long idx = ((long long)(b * QQ + q)) * GG + g0 + tx;

        float x = sem[((long long)(b * QQ + q)) * CC + l];
        float p   = 1.0f / (1.0f + expf(-x));
        float neg = 0.75f * p * p * (-log1pf(-(p - 1e-8f)));
        float pos = 0.25f * (1.0f - p) * (1.0f - p) * (-logf(p + 1e-8f));
        float cost = 2.0f * (pos - neg) + 5.0f * cen[idx] + siz[idx]
                     - 2.0f * gio[idx];

        out_cost[idx] = cost;
        tile[ql][tx]  = cost;
    }
    __syncthreads();

    #pragma unroll
    for (int s = 0; s < 4; ++s) {
        int gl = ty + 8 * s;
        g_costT[((long long)(b * GG + g0 + gl)) * QQ + q0 + tx] = tile[tx][gl];
    }
}

// ---------------------------------------------------------------------------
// Kernel 2: per (b,row) bitonic sort of 2048 packed keys (1024 threads,
// 1 compare-exchange pair per thread per phase); keep TOPK.
// ---------------------------------------------------------------------------
__global__ void __launch_bounds__(1024)
sort_kernel() {
    __shared__ unsigned long long s[QQ];
    int tid = threadIdx.x;
    const float* rowp = g_costT + (size_t)blockIdx.x * QQ;

    #pragma unroll
    for (int t = 0; t < QQ / 1024; ++t) {
        int j = tid + t * 1024;
        s[j] = ((unsigned long long)ord32(rowp[j]) << 32) | (unsigned int)(j + 1);
    }
    __syncthreads();

    for (int k = 2; k <= QQ; k <<= 1) {
        for (int jj = k >> 1; jj > 0; jj >>= 1) {
            // each thread owns one pair: insert jj-bit into tid
            int low = tid & (jj - 1);
            int i   = ((tid & ~(jj - 1)) << 1) | low;
            int l   = i | jj;
            unsigned long long a = s[i], c = s[l];
            bool asc = ((i & k) == 0);
            if (asc ? (a > c) : (a < c)) { s[i] = c; s[l] = a; }
            __syncthreads();
        }
    }
    if (tid < TOPK)
        g_top[(size_t)blockIdx.x * TOPK + tid] = s[tid];
}

// ---------------------------------------------------------------------------
// Kernel 3: one warp per batch; reference's degenerate e-maxx loop.
// NEW: the entire sorted top-list lives in shared memory (~131KB), so probe
// refreshes never touch global memory. Packed-key argmin (col in low 12 bits)
// with 2x REDUX. ~213KB dynamic smem, 1 CTA/SM (only 8 CTAs exist).
// ---------------------------------------------------------------------------
struct SmemLSA {
    unsigned long long top_s[GG * TOPK];   // 131072 B, 16B-aligned (first)
    float  Mc[GG * MCW];                   // row-major [row-1][slot]
    double u_s[GG + 2];
    double Dj[GG + 4];
    int    chain_slot[GG + 4];
    int    chain_row[GG + 4];
    int    pc_col[GG + 2];        // cached first-unmatched col per row (0=none)
    float  pc_val[GG + 2];
    int    cursor[GG + 2];
    unsigned int colinfo[QQ + 4]; // 0 = unmatched; else 0x80000000|slot|(row<<8)
};

__global__ void __launch_bounds__(32, 1)
lsa_kernel(const int* __restrict__ nactual,
           const float* __restrict__ cost_bqg,
           float* __restrict__ out_inds,
           float* __restrict__ out_mask) {
    extern __shared__ unsigned char smraw[];
    SmemLSA& S = *reinterpret_cast<SmemLSA*>(smraw);

    const unsigned FULL = 0xffffffffu;
    int b    = blockIdx.x;
    int lane = threadIdx.x;
    int n = nactual[b];
    if (n > GG) n = GG;
    if (n < 0) n = 0;

    // preload the full sorted top-list into shared (16B vectorized, coalesced)
    {
        const ulonglong2* src =
            (const ulonglong2*)(g_top + (size_t)b * GG * TOPK);
        ulonglong2* dst = (ulonglong2*)S.top_s;
        #pragma unroll 8
        for (int t = lane; t < GG * TOPK / 2; t += 32)
            dst[t] = __ldg(&src[t]);
    }
    for (int t = lane; t < GG + 2; t += 32) {
        S.u_s[t] = 0.0; S.pc_col[t] = 0; S.cursor[t] = 0;
    }
    for (int t = lane; t < QQ + 4; t += 32) S.colinfo[t] = 0u;
    __syncwarp();

    const float* costb = cost_bqg + (size_t)b * QQ * GG;

    // Per-lane slot state: lane owns slots 4*lane .. 4*lane+3.
    double v_r[4];
    int    col_r[4];
    int mcount = 0;

    for (int i = 1; i <= n; ++i) {
        unsigned um = 0;
        int cl = 1, row = i, j1;
        double D = 0.0;
        if (lane == 0) { S.chain_row[0] = i; S.Dj[0] = 0.0; }
        __syncwarp();

        while (true) {
            // --- probe: cached first-unmatched entry; refresh from SMEM ---
            int pcc = S.pc_col[row];
            if (pcc == 0) {
                const unsigned long long* trow = S.top_s + (row - 1) * TOPK;
                int cur = S.cursor[row];
                for (int r = cur >> 5; r < TOPK / 32; ++r) {
                    unsigned long long e = trow[r * 32 + lane];
                    int c = (int)(unsigned int)(e & 0xFFFFFFFFu);
                    unsigned m = __ballot_sync(FULL, S.colinfo[c] == 0u);
                    if (m) {
                        int f = __ffs(m) - 1;
                        unsigned long long ew = __shfl_sync(FULL, e, f);
                        if (lane == 0) {
                            S.pc_col[row] = (int)(unsigned int)(ew & 0xFFFFFFFFu);
                            S.pc_val[row] = unord32((unsigned int)(ew >> 32));
                            S.cursor[row] = r * 32 + f;
                        }
                        break;
                    }
                }
                __syncwarp();
                pcc = S.pc_col[row];
            }
            float  pval  = S.pc_val[row];
            double u_row = S.u_s[row];

            // --- matched-slot keys: one LDS.128, v in regs (u_row cancels),
            //     col packed into low 12 bits of the ord64 key ---
            const float4 mc = *(const float4*)&S.Mc[(row - 1) * MCW + 4 * lane];
            unsigned long long k[4];
            int base = 4 * lane;
            {
                float mcf[4] = {mc.x, mc.y, mc.z, mc.w};
                #pragma unroll
                for (int t = 0; t < 4; ++t) {
                    bool act = (base + t < mcount) && !((um >> t) & 1u);
                    k[t] = act ? ((ord64((double)mcf[t] - v_r[t]) & ~0xFFFull)
                                  | (unsigned)col_r[t])
                               : ~0ull;
                }
            }
            unsigned long long a0 = (k[0] < k[1]) ? k[0] : k[1];
            unsigned long long a1 = (k[2] < k[3]) ? k[2] : k[3];
            unsigned long long bk = (a0 < a1) ? a0 : a1;
            if (lane == 0) {
                unsigned long long kp =
                    (ord64((double)pval) & ~0xFFFull) | (unsigned)pcc;
                if (kp < bk) bk = kp;
            }

            // --- 2-stage REDUX argmin (col tie-break baked into key) ---
            unsigned hi   = (unsigned)(bk >> 32);
            unsigned hmin = __reduce_min_sync(FULL, hi);
            unsigned lo   = (hi == hmin) ? (unsigned)bk : 0xFFFFFFFFu;
            unsigned lmin = __reduce_min_sync(FULL, lo);

            j1 = (int)(lmin & 0xFFFu);
            unsigned long long gmin =
                (((unsigned long long)hmin << 32) | lmin) & ~0xFFFull;
            D += unord64(gmin) - u_row;

            unsigned info = S.colinfo[j1];
            if (info) {                   // chase occupied column
                int slot1 = (int)(info & 0xFFu);
                int nrow  = (int)((info >> 8) & 0xFFu);
                if ((slot1 >> 2) == lane) um |= 1u << (slot1 & 3);
                if (lane == 0) {
                    S.chain_slot[cl] = slot1;
                    S.chain_row[cl]  = nrow;
                    S.Dj[cl]         = D;
                }
                row = nrow;
                ++cl;
            } else break;                 // free column: augment
        }
        __syncwarp();

        // ---- augmentation (off critical path) ----
        // Mc fill: column j1 of costb into Mc[*][mcount]
        {
            const float* colp = costb + (size_t)(j1 - 1) * GG;
            #pragma unroll
            for (int m = 0; m < 4; ++m) {
                int r = lane + 32 * m;
                S.Mc[r * MCW + mcount] = __ldg(&colp[r]);
            }
        }
        // deferred u updates (chain rows distinct)
        for (int t = lane; t < cl; t += 32) {
            S.u_s[S.chain_row[t]] += D - S.Dj[t];
        }
        // deferred v updates: each lane applies chain entries owning its slots
        for (int t = 1; t < cl; ++t) {
            int s = S.chain_slot[t];
            if ((s >> 2) == lane) {
                double acc = D - S.Dj[t];
                switch (s & 3) {
                    case 0: v_r[0] -= acc; break;
                    case 1: v_r[1] -= acc; break;
                    case 2: v_r[2] -= acc; break;
                    case 3: v_r[3] -= acc; break;
                }
            }
        }
        // invalidate probe caches pointing at the newly matched column
        #pragma unroll
        for (int t = 0; t < 4; ++t) {
            int r = 1 + lane + 32 * t;
            if (S.pc_col[r] == j1) S.pc_col[r] = 0;
        }
        // register the new slot
        if ((mcount >> 2) == lane) {
            switch (mcount & 3) {
                case 0: v_r[0] = 0.0; col_r[0] = j1; break;
                case 1: v_r[1] = 0.0; col_r[1] = j1; break;
                case 2: v_r[2] = 0.0; col_r[2] = j1; break;
                case 3: v_r[3] = 0.0; col_r[3] = j1; break;
            }
        }
        if (lane == 0) {
            S.colinfo[j1] = 0x80000000u | (unsigned)mcount | ((unsigned)i << 8);
        }
        ++mcount;
        __syncwarp();
    }

    // emit per-proposal matches
    for (int j = lane; j < QQ; j += 32) {
        unsigned info = S.colinfo[j + 1];
        float ind = 0.0f, mskv = 0.0f;
        if (info) { ind = (float)(((info >> 8) & 0xFFu) - 1); mskv = 1.0f; }
        out_inds[b * QQ + j] = ind;
        out_mask[b * QQ + j] = mskv;
    }
}

// ---------------------------------------------------------------------------
extern "C" void kernel_launch(void* const* d_in, const int* in_sizes, int n_in,
                              void* d_out, int out_size) {
    const float* sem = (const float*)d_in[0];
    const float* cen = (const float*)d_in[1];
    const float* siz = (const float*)d_in[2];
    const float* gio = (const float*)d_in[3];
    const int*   lab = (const int*)d_in[4];
    const int*   na  = (const int*)d_in[5];

    float* out = (float*)d_out;
    const int NI = BB * QQ;
    const int NC = BB * QQ * GG;

    float* out_inds = out;
    float* out_mask = out + NI;
    float* out_cost = out + 2 * NI;
    bool   do_lsa   = true;
    if (out_size == NC) { out_cost = out; do_lsa = false; }

    cost_kernel<<<BB * 4 * 64, 256>>>(sem, cen, siz, gio, lab, out_cost);
    if (do_lsa) {
        sort_kernel<<<BB * GG, 1024>>>();
        static bool attr_set = false;
        if (!attr_set) {
            cudaFuncSetAttribute(lsa_kernel,
                                 cudaFuncAttributeMaxDynamicSharedMemorySize,
                                 (int)sizeof(SmemLSA));
            attr_set = true;
        }
        lsa_kernel<<<BB, 32, sizeof(SmemLSA)>>>(na, out_cost, out_inds, out_mask);
    }
}

// round 10
// speedup vs baseline: 1.1477x; 1.0062x over previous
#include <cuda_runtime.h>
#include <math.h>

#define BB 8
#define QQ 2048
#define GG 128
#define CC 512
#define TOPK 128     // exactly sufficient: <=127 cols matched at probe time
#define MCW 136      // Mc row stride (floats): 16B-aligned float4, conflict-free
#define M26 0x3FFFFFFull   // low 26 key bits: col(12)|row(7)|slot(7)

// Transposed cost scratch: [b][g][q], contiguous in q (feeds the sort).
__device__ float g_costT[BB * GG * QQ];
// Per (b,row) sorted smallest-TOPK entries, packed (ord32(val)<<32)|col(1-based).
__device__ unsigned long long g_top[BB * GG * TOPK];

// ---------------------------------------------------------------------------
__device__ __forceinline__ unsigned int ord32(float f) {
    unsigned int u = __float_as_uint(f);
    return (u & 0x80000000u) ? ~u : (u | 0x80000000u);
}
__device__ __forceinline__ float unord32(unsigned int o) {
    unsigned int u = (o & 0x80000000u) ? (o ^ 0x80000000u) : ~o;
    return __uint_as_float(u);
}
__device__ __forceinline__ unsigned long long ord64(double d) {
    unsigned long long u = (unsigned long long)__double_as_longlong(d);
    return (u >> 63) ? ~u : (u | 0x8000000000000000ull);
}
__device__ __forceinline__ double unord64(unsigned long long o) {
    unsigned long long u = (o >> 63) ? (o ^ 0x8000000000000000ull) : ~o;
    return __longlong_as_double((long long)u);
}

// ---------------------------------------------------------------------------
// Kernel 1: fused focal-class cost + regression costs, tiled transpose.
// ---------------------------------------------------------------------------
__global__ void __launch_bounds__(256)
cost_kernel(const float* __restrict__ sem,
            const float* __restrict__ cen,
            const float* __restrict__ siz,
            const float* __restrict__ gio,
            const int* __restrict__ lab,
            float* __restrict__ out_cost) {
    __shared__ float tile[32][33];
    __shared__ int   lab_s[32];

    int blk = blockIdx.x;                 // (b * 4 + gt) * 64 + qt
    int qt  = blk & 63;
    int gt  = (blk >> 6) & 3;
    int b   = blk >> 8;

    int tx = threadIdx.x & 31;            // g within tile
    int ty = threadIdx.x >> 5;            // q sub-row (0..7)
    int g0 = gt * 32;
    int q0 = qt * 32;

    if (threadIdx.x < 32) lab_s[tx] = lab[b * GG + g0 + tx];
    __syncthreads();

    int l = lab_s[tx];
    #pragma unroll
    for (int s = 0; s < 4; ++s) {
        int ql = ty + 8 * s;
        int q  = q0 + ql;
        long long idx = ((long long)(b * QQ + q)) * GG + g0 + tx;

        float x = sem[((long long)(b * QQ + q)) * CC + l];
        float p   = 1.0f / (1.0f + expf(-x));
        float neg = 0.75f * p * p * (-log1pf(-(p - 1e-8f)));
        float pos = 0.25f * (1.0f - p) * (1.0f - p) * (-logf(p + 1e-8f));
        float cost = 2.0f * (pos - neg) + 5.0f * cen[idx] + siz[idx]
                     - 2.0f * gio[idx];

        out_cost[idx] = cost;
        tile[ql][tx]  = cost;
    }
    __syncthreads();

    #pragma unroll
    for (int s = 0; s < 4; ++s) {
        int gl = ty + 8 * s;
        g_costT[((long long)(b * GG + g0 + gl)) * QQ + q0 + tx] = tile[tx][gl];
    }
}

// ---------------------------------------------------------------------------
// Kernel 2: per (b,row) bitonic sort of 2048 packed keys. Phases jj>=32 in
// shared; phases jj<=16 in registers via shfl (no barriers). Keep TOPK.
// ---------------------------------------------------------------------------
__global__ void __launch_bounds__(1024)
sort_kernel() {
    __shared__ unsigned long long s[QQ];
    const unsigned FULL = 0xffffffffu;
    int tid = threadIdx.x;
    const float* rowp = g_costT + (size_t)blockIdx.x * QQ;

    s[tid] = ((unsigned long long)ord32(rowp[tid]) << 32) |
             (unsigned int)(tid + 1);
    s[tid + 1024] = ((unsigned long long)ord32(rowp[tid + 1024]) << 32) |
                    (unsigned int)(tid + 1024 + 1);
    __syncthreads();

    for (int k = 2; k <= QQ; k <<= 1) {
        // shared-memory phases (cross-warp partners)
        for (int jj = k >> 1; jj >= 32; jj >>= 1) {
            int low = tid & (jj - 1);
            int i   = ((tid & ~(jj - 1)) << 1) | low;
            int l   = i | jj;
            unsigned long long a = s[i], c = s[l];
            bool asc = ((i & k) == 0);
            if (asc ? (a > c) : (a < c)) { s[i] = c; s[l] = a; }
            __syncthreads();
        }
        // register/shfl phases (partners within warp)
        int idx0 = tid, idx1 = tid + 1024;
        unsigned long long e0 = s[idx0], e1 = s[idx1];
        bool asc0 = ((idx0 & k) == 0);
        bool asc1 = ((idx1 & k) == 0);
        int jj0 = (k >> 1 < 32) ? (k >> 1) : 16;
        for (int jj = jj0; jj > 0; jj >>= 1) {
            unsigned long long p0 = __shfl_xor_sync(FULL, e0, jj);
            unsigned long long p1 = __shfl_xor_sync(FULL, e1, jj);
            bool keepmin0 = (((idx0 & jj) == 0) == asc0);
            bool keepmin1 = (((idx1 & jj) == 0) == asc1);
            if (keepmin0 ? (p0 < e0) : (p0 > e0)) e0 = p0;
            if (keepmin1 ? (p1 < e1) : (p1 > e1)) e1 = p1;
        }
        s[idx0] = e0; s[idx1] = e1;
        __syncthreads();
    }
    if (tid < TOPK)
        g_top[(size_t)blockIdx.x * TOPK + tid] = s[tid];
}

// ---------------------------------------------------------------------------
// Kernel 3: one warp per batch; reference's degenerate e-maxx loop.
// Key low 26 bits carry col|owner_row|slot, so the winner of the 2x REDUX
// directly yields the next row/slot — no dependent colinfo lookup in the loop.
// ---------------------------------------------------------------------------
struct SmemLSA {
    unsigned long long top_s[GG * TOPK];   // 131072 B (16B-aligned first)
    float  Mc[GG * MCW];                   // row-major [row-1][slot]
    double u_s[GG + 2];
    double Dj[GG + 4];
    int    chain_slot[GG + 4];
    int    chain_row[GG + 4];
    int    pc_col[GG + 2];        // cached first-unmatched col per row (0=none)
    float  pc_val[GG + 2];
    int    cursor[GG + 2];
    unsigned int colinfo[QQ + 4]; // 0 = unmatched; else row (for ballot/emit)
};

__global__ void __launch_bounds__(32, 1)
lsa_kernel(const int* __restrict__ nactual,
           const float* __restrict__ cost_bqg,
           float* __restrict__ out_inds,
           float* __restrict__ out_mask) {
    extern __shared__ unsigned char smraw[];
    SmemLSA& S = *reinterpret_cast<SmemLSA*>(smraw);

    const unsigned FULL = 0xffffffffu;
    int b    = blockIdx.x;
    int lane = threadIdx.x;
    int n = nactual[b];
    if (n > GG) n = GG;
    if (n < 0) n = 0;

    // preload the full sorted top-list into shared (16B vectorized, coalesced)
    {
        const ulonglong2* src =
            (const ulonglong2*)(g_top + (size_t)b * GG * TOPK);
        ulonglong2* dst = (ulonglong2*)S.top_s;
        #pragma unroll 8
        for (int t = lane; t < GG * TOPK / 2; t += 32)
            dst[t] = __ldg(&src[t]);
    }
    for (int t = lane; t < GG + 2; t += 32) {
        S.u_s[t] = 0.0; S.pc_col[t] = 0; S.cursor[t] = 0;
    }
    for (int t = lane; t < QQ + 4; t += 32) S.colinfo[t] = 0u;
    __syncwarp();

    const float* costb = cost_bqg + (size_t)b * QQ * GG;

    // Per-lane slot state: lane owns slots 4*lane .. 4*lane+3.
    double   v_r[4];
    unsigned low_r[4];            // precomputed col<<14 | (row-1)<<7 | slot
    int mcount = 0;

    for (int i = 1; i <= n; ++i) {
        unsigned um = 0;
        int cl = 1, row = i, j1;
        double D = 0.0;
        if (lane == 0) { S.chain_row[0] = i; S.Dj[0] = 0.0; }
        __syncwarp();

        while (true) {
            // --- probe: cached first-unmatched entry; refresh from SMEM ---
            int   pcc;
            float pval;
            {
                int c0 = S.pc_col[row];
                if (c0 != 0) {
                    pcc = c0; pval = S.pc_val[row];
                } else {
                    const unsigned long long* trow = S.top_s + (row - 1) * TOPK;
                    int cur = S.cursor[row];
                    unsigned long long ew = 0;
                    for (int r = cur >> 5; r < TOPK / 32; ++r) {
                        unsigned long long e = trow[r * 32 + lane];
                        int c = (int)(unsigned int)(e & 0xFFFFFFFFu);
                        unsigned m = __ballot_sync(FULL, S.colinfo[c] == 0u);
                        if (m) {
                            int f = __ffs(m) - 1;
                            ew = __shfl_sync(FULL, e, f);
                            if (lane == 0) S.cursor[row] = r * 32 + f;
                            break;
                        }
                    }
                    pcc  = (int)(unsigned int)(ew & 0xFFFFFFFFu);
                    pval = unord32((unsigned int)(ew >> 32));
                    if (lane == 0) {
                        S.pc_col[row] = pcc;
                        S.pc_val[row] = pval;
                    }
                    __syncwarp();
                }
            }
            double u_row = S.u_s[row];

            // --- matched-slot keys: one LDS.128, v in regs (u_row cancels),
            //     col|row|slot packed into low 26 bits of the ord64 key ---
            const float4 mc = *(const float4*)&S.Mc[(row - 1) * MCW + 4 * lane];
            unsigned long long k[4];
            int base = 4 * lane;
            {
                float mcf[4] = {mc.x, mc.y, mc.z, mc.w};
                #pragma unroll
                for (int t = 0; t < 4; ++t) {
                    bool act = (base + t < mcount) && !((um >> t) & 1u);
                    k[t] = act ? ((ord64((double)mcf[t] - v_r[t]) & ~M26)
                                  | low_r[t])
                               : ~0ull;
                }
            }
            unsigned long long a0 = (k[0] < k[1]) ? k[0] : k[1];
            unsigned long long a1 = (k[2] < k[3]) ? k[2] : k[3];
            unsigned long long bk = (a0 < a1) ? a0 : a1;
            if (lane == 0) {
                unsigned long long kp = (ord64((double)pval) & ~M26)
                                        | ((unsigned)pcc << 14) | 0x7Fu;
                if (kp < bk) bk = kp;
            }

            // --- 2-stage REDUX argmin (col tie-break baked into key) ---
            unsigned hi   = (unsigned)(bk >> 32);
            unsigned hmin = __reduce_min_sync(FULL, hi);
            unsigned lo   = (hi == hmin) ? (unsigned)bk : 0xFFFFFFFFu;
            unsigned lmin = __reduce_min_sync(FULL, lo);

            int slot1 = (int)(lmin & 0x7Fu);
            j1 = (int)((lmin >> 14) & 0xFFFu);
            unsigned long long gmin =
                (((unsigned long long)hmin << 32) | lmin) & ~M26;
            D += unord64(gmin) - u_row;

            if (slot1 != 0x7F) {          // chase occupied column
                int nrow = (int)((lmin >> 7) & 0x7Fu) + 1;
                if ((slot1 >> 2) == lane) um |= 1u << (slot1 & 3);
                if (lane == 0) {
                    S.chain_slot[cl] = slot1;
                    S.chain_row[cl]  = nrow;
                    S.Dj[cl]         = D;
                }
                row = nrow;
                ++cl;
            } else break;                 // free column: augment
        }
        __syncwarp();

        // ---- augmentation (off critical path) ----
        // Mc fill: column j1 of costb into Mc[*][mcount]
        {
            const float* colp = costb + (size_t)(j1 - 1) * GG;
            #pragma unroll
            for (int m = 0; m < 4; ++m) {
                int r = lane + 32 * m;
                S.Mc[r * MCW + mcount] = __ldg(&colp[r]);
            }
        }
        // deferred u updates (chain rows distinct)
        for (int t = lane; t < cl; t += 32) {
            S.u_s[S.chain_row[t]] += D - S.Dj[t];
        }
        // deferred v updates: each lane applies chain entries owning its slots
        for (int t = 1; t < cl; ++t) {
            int s = S.chain_slot[t];
            if ((s >> 2) == lane) {
                double acc = D - S.Dj[t];
                switch (s & 3) {
                    case 0: v_r[0] -= acc; break;
                    case 1: v_r[1] -= acc; break;
                    case 2: v_r[2] -= acc; break;
                    case 3: v_r[3] -= acc; break;
                }
            }
        }
        // invalidate probe caches pointing at the newly matched column
        #pragma unroll
        for (int t = 0; t < 4; ++t) {
            int r = 1 + lane + 32 * t;
            if (S.pc_col[r] == j1) S.pc_col[r] = 0;
        }
        // register the new slot (low bits precomputed for key packing)
        if ((mcount >> 2) == lane) {
            unsigned lw = ((unsigned)j1 << 14) | ((unsigned)(i - 1) << 7)
                          | (unsigned)mcount;
            switch (mcount & 3) {
                case 0: v_r[0] = 0.0; low_r[0] = lw; break;
                case 1: v_r[1] = 0.0; low_r[1] = lw; break;
                case 2: v_r[2] = 0.0; low_r[2] = lw; break;
                case 3: v_r[3] = 0.0; low_r[3] = lw; break;
            }
        }
        if (lane == 0) S.colinfo[j1] = (unsigned)i;   // row, for ballot/emit
        ++mcount;
        __syncwarp();
    }

    // emit per-proposal matches
    for (int j = lane; j < QQ; j += 32) {
        unsigned info = S.colinfo[j + 1];
        float ind = 0.0f, mskv = 0.0f;
        if (info) { ind = (float)(info - 1); mskv = 1.0f; }
        out_inds[b * QQ + j] = ind;
        out_mask[b * QQ + j] = mskv;
    }
}

// ---------------------------------------------------------------------------
extern "C" void kernel_launch(void* const* d_in, const int* in_sizes, int n_in,
                              void* d_out, int out_size) {
    const float* sem = (const float*)d_in[0];
    const float* cen = (const float*)d_in[1];
    const float* siz = (const float*)d_in[2];
    const float* gio = (const float*)d_in[3];
    const int*   lab = (const int*)d_in[4];
    const int*   na  = (const int*)d_in[5];

    float* out = (float*)d_out;
    const int NI = BB * QQ;
    const int NC = BB * QQ * GG;

    float* out_inds = out;
    float* out_mask = out + NI;
    float* out_cost = out + 2 * NI;
    bool   do_lsa   = true;
    if (out_size == NC) { out_cost = out; do_lsa = false; }

    cost_kernel<<<BB * 4 * 64, 256>>>(sem, cen, siz, gio, lab, out_cost);
    if (do_lsa) {
        sort_kernel<<<BB * GG, 1024>>>();
        static bool attr_set = false;
        if (!attr_set) {
            cudaFuncSetAttribute(lsa_kernel,
                                 cudaFuncAttributeMaxDynamicSharedMemorySize,
                                 (int)sizeof(SmemLSA));
            attr_set = true;
        }
        lsa_kernel<<<BB, 32, sizeof(SmemLSA)>>>(na, out_cost, out_inds, out_mask);
    }
}

// round 11
// speedup vs baseline: 1.3398x; 1.1674x over previous
#include <cuda_runtime.h>
#include <math.h>

#define BB 8
#define QQ 2048
#define GG 128
#define CC 512
#define TOPK 128     // exactly sufficient: <=127 cols matched at probe time
#define MCW 136      // Mc row stride (floats): 16B-aligned float4, conflict-free
#define M26 0x3FFFFFFull   // low 26 key bits: col(12)|row(7)|slot(7)
#define EPS_AMB 1e-3f      // fp32-selection safety margin (10x worst-case err)

// Transposed cost scratch: [b][g][q], contiguous in q (feeds the sort).
__device__ float g_costT[BB * GG * QQ];
// Per (b,row) sorted smallest-TOPK entries, packed (ord32(val)<<32)|col(1-based).
__device__ unsigned long long g_top[BB * GG * TOPK];

// ---------------------------------------------------------------------------
__device__ __forceinline__ unsigned int ord32(float f) {
    unsigned int u = __float_as_uint(f);
    return (u & 0x80000000u) ? ~u : (u | 0x80000000u);
}
__device__ __forceinline__ float unord32(unsigned int o) {
    unsigned int u = (o & 0x80000000u) ? (o ^ 0x80000000u) : ~o;
    return __uint_as_float(u);
}
__device__ __forceinline__ unsigned long long ord64(double d) {
    unsigned long long u = (unsigned long long)__double_as_longlong(d);
    return (u >> 63) ? ~u : (u | 0x8000000000000000ull);
}

// ---------------------------------------------------------------------------
// Kernel 1: fused focal-class cost + regression costs, tiled transpose.
// ---------------------------------------------------------------------------
__global__ void __launch_bounds__(256)
cost_kernel(const float* __restrict__ sem,
            const float* __restrict__ cen,
            const float* __restrict__ siz,
            const float* __restrict__ gio,
            const int* __restrict__ lab,
            float* __restrict__ out_cost) {
    __shared__ float tile[32][33];
    __shared__ int   lab_s[32];

    int blk = blockIdx.x;                 // (b * 4 + gt) * 64 + qt
    int qt  = blk & 63;
    int gt  = (blk >> 6) & 3;
    int b   = blk >> 8;

    int tx = threadIdx.x & 31;            // g within tile
    int ty = threadIdx.x >> 5;            // q sub-row (0..7)
    int g0 = gt * 32;
    int q0 = qt * 32;

    if (threadIdx.x < 32) lab_s[tx] = lab[b * GG + g0 + tx];
    __syncthreads();

    int l = lab_s[tx];
    #pragma unroll
    for (int s = 0; s < 4; ++s) {
        int ql = ty + 8 * s;
        int q  = q0 + ql;
        long long idx = ((long long)(b * QQ + q)) * GG + g0 + tx;

        float x = sem[((long long)(b * QQ + q)) * CC + l];
        float p   = 1.0f / (1.0f + expf(-x));
        float neg = 0.75f * p * p * (-log1pf(-(p - 1e-8f)));
        float pos = 0.25f * (1.0f - p) * (1.0f - p) * (-logf(p + 1e-8f));
        float cost = 2.0f * (pos - neg) + 5.0f * cen[idx] + siz[idx]
                     - 2.0f * gio[idx];

        out_cost[idx] = cost;
        tile[ql][tx]  = cost;
    }
    __syncthreads();

    #pragma unroll
    for (int s = 0; s < 4; ++s) {
        int gl = ty + 8 * s;
        g_costT[((long long)(b * GG + g0 + gl)) * QQ + q0 + tx] = tile[tx][gl];
    }
}

// ---------------------------------------------------------------------------
// Kernel 2: per (b,row) bitonic sort of 2048 packed keys. Phases jj>=32 in
// shared; phases jj<=16 in registers via shfl (no barriers). Keep TOPK.
// ---------------------------------------------------------------------------
__global__ void __launch_bounds__(1024)
sort_kernel() {
    __shared__ unsigned long long s[QQ];
    const unsigned FULL = 0xffffffffu;
    int tid = threadIdx.x;
    const float* rowp = g_costT + (size_t)blockIdx.x * QQ;

    s[tid] = ((unsigned long long)ord32(rowp[tid]) << 32) |
             (unsigned int)(tid + 1);
    s[tid + 1024] = ((unsigned long long)ord32(rowp[tid + 1024]) << 32) |
                    (unsigned int)(tid + 1024 + 1);
    __syncthreads();

    for (int k = 2; k <= QQ; k <<= 1) {
        for (int jj = k >> 1; jj >= 32; jj >>= 1) {
            int low = tid & (jj - 1);
            int i   = ((tid & ~(jj - 1)) << 1) | low;
            int l   = i | jj;
            unsigned long long a = s[i], c = s[l];
            bool asc = ((i & k) == 0);
            if (asc ? (a > c) : (a < c)) { s[i] = c; s[l] = a; }
            __syncthreads();
        }
        int idx0 = tid, idx1 = tid + 1024;
        unsigned long long e0 = s[idx0], e1 = s[idx1];
        bool asc0 = ((idx0 & k) == 0);
        bool asc1 = ((idx1 & k) == 0);
        int jj0 = (k >> 1 < 32) ? (k >> 1) : 16;
        for (int jj = jj0; jj > 0; jj >>= 1) {
            unsigned long long p0 = __shfl_xor_sync(FULL, e0, jj);
            unsigned long long p1 = __shfl_xor_sync(FULL, e1, jj);
            bool keepmin0 = (((idx0 & jj) == 0) == asc0);
            bool keepmin1 = (((idx1 & jj) == 0) == asc1);
            if (keepmin0 ? (p0 < e0) : (p0 > e0)) e0 = p0;
            if (keepmin1 ? (p1 < e1) : (p1 > e1)) e1 = p1;
        }
        s[idx0] = e0; s[idx1] = e1;
        __syncthreads();
    }
    if (tid < TOPK)
        g_top[(size_t)blockIdx.x * TOPK + tid] = s[tid];
}

// ---------------------------------------------------------------------------
// Kernel 3: one warp per batch; reference's degenerate e-maxx loop.
// fp32 fast-path selection with exact-fp64 ambiguity fallback; exact fp64
// accounting (D, u, v) via owner-lane recompute+shfl, off the critical path.
// ---------------------------------------------------------------------------
struct SmemLSA {
    unsigned long long top_s[GG * TOPK];   // 131072 B (16B-aligned first)
    float  Mc[GG * MCW];                   // row-major [row-1][slot]
    double u_s[GG + 2];
    double Dj[GG + 4];
    int    chain_slot[GG + 4];
    int    chain_row[GG + 4];
    int    pc_col[GG + 2];        // cached first-unmatched col per row (0=none)
    float  pc_val[GG + 2];
    int    cursor[GG + 2];
    unsigned int colinfo[QQ + 4]; // 0 = unmatched; else row (for ballot/emit)
};

__global__ void __launch_bounds__(32, 1)
lsa_kernel(const int* __restrict__ nactual,
           const float* __restrict__ cost_bqg,
           float* __restrict__ out_inds,
           float* __restrict__ out_mask) {
    extern __shared__ unsigned char smraw[];
    SmemLSA& S = *reinterpret_cast<SmemLSA*>(smraw);

    const unsigned FULL = 0xffffffffu;
    int b    = blockIdx.x;
    int lane = threadIdx.x;
    int n = nactual[b];
    if (n > GG) n = GG;
    if (n < 0) n = 0;

    // preload the full sorted top-list into shared (16B vectorized, coalesced)
    {
        const ulonglong2* src =
            (const ulonglong2*)(g_top + (size_t)b * GG * TOPK);
        ulonglong2* dst = (ulonglong2*)S.top_s;
        #pragma unroll 8
        for (int t = lane; t < GG * TOPK / 2; t += 32)
            dst[t] = __ldg(&src[t]);
    }
    for (int t = lane; t < GG + 2; t += 32) {
        S.u_s[t] = 0.0; S.pc_col[t] = 0; S.cursor[t] = 0;
    }
    for (int t = lane; t < QQ + 4; t += 32) S.colinfo[t] = 0u;
    __syncwarp();

    const float* costb = cost_bqg + (size_t)b * QQ * GG;

    // Per-lane slot state: lane owns slots 4*lane .. 4*lane+3.
    double   v_r[4];
    float    vf_r[4];
    unsigned low_r[4];            // col<<14 | (row-1)<<7 | slot
    int mcount = 0;

    for (int i = 1; i <= n; ++i) {
        unsigned um = 0;
        int cl = 1, row = i, j1;
        double D = 0.0;
        if (lane == 0) { S.chain_row[0] = i; S.Dj[0] = 0.0; }
        __syncwarp();

        while (true) {
            // --- probe: cached first-unmatched entry; refresh from SMEM ---
            int   pcc;
            float pval;
            {
                int c0 = S.pc_col[row];
                if (c0 != 0) {
                    pcc = c0; pval = S.pc_val[row];
                } else {
                    const unsigned long long* trow = S.top_s + (row - 1) * TOPK;
                    int cur = S.cursor[row];
                    unsigned long long ew = 0;
                    for (int r = cur >> 5; r < TOPK / 32; ++r) {
                        unsigned long long e = trow[r * 32 + lane];
                        int c = (int)(unsigned int)(e & 0xFFFFFFFFu);
                        unsigned m = __ballot_sync(FULL, S.colinfo[c] == 0u);
                        if (m) {
                            int f = __ffs(m) - 1;
                            ew = __shfl_sync(FULL, e, f);
                            if (lane == 0) S.cursor[row] = r * 32 + f;
                            break;
                        }
                    }
                    pcc  = (int)(unsigned int)(ew & 0xFFFFFFFFu);
                    pval = unord32((unsigned int)(ew >> 32));
                    if (lane == 0) {
                        S.pc_col[row] = pcc;
                        S.pc_val[row] = pval;
                    }
                    __syncwarp();
                }
            }
            double u_row = S.u_s[row];

            // --- fp32 fast keys: one LDS.128 + FADD, packed (ord32|id26) ---
            const float4 mc = *(const float4*)&S.Mc[(row - 1) * MCW + 4 * lane];
            float mcf[4] = {mc.x, mc.y, mc.z, mc.w};
            bool  act[4];
            float kf[4];
            unsigned long long kk[4];
            int base = 4 * lane;
            #pragma unroll
            for (int t = 0; t < 4; ++t) {
                act[t] = (base + t < mcount) && !((um >> t) & 1u);
                kf[t]  = act[t] ? (mcf[t] - vf_r[t]) : __int_as_float(0x7F800000);
                kk[t]  = ((unsigned long long)ord32(kf[t]) << 32) | low_r[t];
            }
            unsigned long long a0 = (kk[0] < kk[1]) ? kk[0] : kk[1];
            unsigned long long a1 = (kk[2] < kk[3]) ? kk[2] : kk[3];
            unsigned long long bk = (a0 < a1) ? a0 : a1;
            if (lane == 0) {
                unsigned long long kp =
                    ((unsigned long long)ord32(pval) << 32)
                    | ((unsigned)pcc << 14) | 0x7Fu;
                if (kp < bk) bk = kp;
            }

            // --- 2-stage REDUX argmin on fp32 keys ---
            unsigned hi   = (unsigned)(bk >> 32);
            unsigned hmin = __reduce_min_sync(FULL, hi);
            unsigned lo   = (hi == hmin) ? (unsigned)bk : 0xFFFFFFFFu;
            unsigned lmin = __reduce_min_sync(FULL, lo);

            // --- ambiguity check (runs alongside): >=2 candidates within EPS ---
            float thr = unord32(hmin) + EPS_AMB;
            unsigned cnt = 0;
            #pragma unroll
            for (int t = 0; t < 4; ++t)
                if (act[t] && kf[t] <= thr) ++cnt;
            if (lane == 0 && pval <= thr) ++cnt;
            unsigned tot = __reduce_add_sync(FULL, cnt);

            if (tot >= 2) {
                // --- exact fp64 fallback (identical to the proven path) ---
                unsigned long long k2[4];
                #pragma unroll
                for (int t = 0; t < 4; ++t)
                    k2[t] = act[t]
                        ? ((ord64((double)mcf[t] - v_r[t]) & ~M26) | low_r[t])
                        : ~0ull;
                unsigned long long c0 = (k2[0] < k2[1]) ? k2[0] : k2[1];
                unsigned long long c1 = (k2[2] < k2[3]) ? k2[2] : k2[3];
                unsigned long long b2 = (c0 < c1) ? c0 : c1;
                if (lane == 0) {
                    unsigned long long kp2 = (ord64((double)pval) & ~M26)
                                             | ((unsigned)pcc << 14) | 0x7Fu;
                    if (kp2 < b2) b2 = kp2;
                }
                unsigned h2  = (unsigned)(b2 >> 32);
                unsigned hm2 = __reduce_min_sync(FULL, h2);
                unsigned l2  = (h2 == hm2) ? (unsigned)b2 : 0xFFFFFFFFu;
                lmin = __reduce_min_sync(FULL, l2);
            }

            int slot1 = (int)(lmin & 0x7Fu);
            j1 = (int)((lmin >> 14) & 0xFFFu);

            // --- exact D update via owner-lane recompute (off critical path) ---
            int owner = (slot1 == 0x7F) ? 0 : (slot1 >> 2);
            double ek = 0.0;
            if (lane == owner) {
                if (slot1 == 0x7F) ek = (double)pval;
                else {
                    int t = slot1 & 3;
                    float mm; double vv;
                    switch (t) {
                        case 0: mm = mcf[0]; vv = v_r[0]; break;
                        case 1: mm = mcf[1]; vv = v_r[1]; break;
                        case 2: mm = mcf[2]; vv = v_r[2]; break;
                        default: mm = mcf[3]; vv = v_r[3]; break;
                    }
                    ek = (double)mm - vv;
                }
            }
            ek = __shfl_sync(FULL, ek, owner);
            D += ek - u_row;

            if (slot1 != 0x7F) {          // chase occupied column
                int nrow = (int)((lmin >> 7) & 0x7Fu) + 1;
                if (owner == lane) um |= 1u << (slot1 & 3);
                if (lane == 0) {
                    S.chain_slot[cl] = slot1;
                    S.chain_row[cl]  = nrow;
                    S.Dj[cl]         = D;
                }
                row = nrow;
                ++cl;
            } else break;                 // free column: augment
        }
        __syncwarp();

        // ---- augmentation (off critical path) ----
        {
            const float* colp = costb + (size_t)(j1 - 1) * GG;
            #pragma unroll
            for (int m = 0; m < 4; ++m) {
                int r = lane + 32 * m;
                S.Mc[r * MCW + mcount] = __ldg(&colp[r]);
            }
        }
        for (int t = lane; t < cl; t += 32) {
            S.u_s[S.chain_row[t]] += D - S.Dj[t];
        }
        for (int t = 1; t < cl; ++t) {
            int s = S.chain_slot[t];
            if ((s >> 2) == lane) {
                double acc = D - S.Dj[t];
                switch (s & 3) {
                    case 0: v_r[0] -= acc; break;
                    case 1: v_r[1] -= acc; break;
                    case 2: v_r[2] -= acc; break;
                    case 3: v_r[3] -= acc; break;
                }
            }
        }
        #pragma unroll
        for (int t = 0; t < 4; ++t) {
            int r = 1 + lane + 32 * t;
            if (S.pc_col[r] == j1) S.pc_col[r] = 0;
        }
        if ((mcount >> 2) == lane) {
            unsigned lw = ((unsigned)j1 << 14) | ((unsigned)(i - 1) << 7)
                          | (unsigned)mcount;
            switch (mcount & 3) {
                case 0: v_r[0] = 0.0; low_r[0] = lw; break;
                case 1: v_r[1] = 0.0; low_r[1] = lw; break;
                case 2: v_r[2] = 0.0; low_r[2] = lw; break;
                case 3: v_r[3] = 0.0; low_r[3] = lw; break;
            }
        }
        // refresh float copies of v (cheap, off path)
        #pragma unroll
        for (int t = 0; t < 4; ++t) vf_r[t] = (float)v_r[t];

        if (lane == 0) S.colinfo[j1] = (unsigned)i;   // row, for ballot/emit
        ++mcount;
        __syncwarp();
    }

    // emit per-proposal matches
    for (int j = lane; j < QQ; j += 32) {
        unsigned info = S.colinfo[j + 1];
        float ind = 0.0f, mskv = 0.0f;
        if (info) { ind = (float)(info - 1); mskv = 1.0f; }
        out_inds[b * QQ + j] = ind;
        out_mask[b * QQ + j] = mskv;
    }
}

// ---------------------------------------------------------------------------
extern "C" void kernel_launch(void* const* d_in, const int* in_sizes, int n_in,
                              void* d_out, int out_size) {
    const float* sem = (const float*)d_in[0];
    const float* cen = (const float*)d_in[1];
    const float* siz = (const float*)d_in[2];
    const float* gio = (const float*)d_in[3];
    const int*   lab = (const int*)d_in[4];
    const int*   na  = (const int*)d_in[5];

    float* out = (float*)d_out;
    const int NI = BB * QQ;
    const int NC = BB * QQ * GG;

    float* out_inds = out;
    float* out_mask = out + NI;
    float* out_cost = out + 2 * NI;
    bool   do_lsa   = true;
    if (out_size == NC) { out_cost = out; do_lsa = false; }

    cost_kernel<<<BB * 4 * 64, 256>>>(sem, cen, siz, gio, lab, out_cost);
    if (do_lsa) {
        sort_kernel<<<BB * GG, 1024>>>();
        static bool attr_set = false;
        if (!attr_set) {
            cudaFuncSetAttribute(lsa_kernel,
                                 cudaFuncAttributeMaxDynamicSharedMemorySize,
                                 (int)sizeof(SmemLSA));
            attr_set = true;
        }
        lsa_kernel<<<BB, 32, sizeof(SmemLSA)>>>(na, out_cost, out_inds, out_mask);
    }
}